// round 4
// baseline (speedup 1.0000x reference)
#include <cuda_runtime.h>
#include <cuda_bf16.h>

// Problem shape (fixed by the reference): pred [16,4,512,512] f32, target/ME [16,512,512] i32
#define NUM_CLASSES 4
#define IGNORE_INDEX 4
#define HW 262144            // 512*512 (pixels per batch)
#define NPIX (16 * HW)       // 4,194,304
#define NVEC (NPIX / 4)      // 1,048,576 float4-groups
#define GRID 4096
#define TPB 256
// NVEC == GRID * TPB exactly -> one group per thread, no loop, no bounds checks

__device__ float2   g_partials[GRID];   // written unconditionally every run -> no init needed
__device__ unsigned g_ticket = 0;       // self-resetting via atomicInc wrap

__device__ __forceinline__ void pixel_nll(float v0, float v1, float v2, float v3,
                                          int t, int me,
                                          float& acc, float& cnt) {
    float m = fmaxf(fmaxf(v0, v1), fmaxf(v2, v3));
    float s = __expf(v0 - m) + __expf(v1 - m) + __expf(v2 - m) + __expf(v3 - m);
    float lse = m + __logf(s);
    int tc = min(t, NUM_CLASSES - 1);
    float vt = (tc == 0) ? v0 : (tc == 1) ? v1 : (tc == 2) ? v2 : v3;
    float nll = lse - vt;
    float w = (me == 0) ? 1.0f : 0.5f;
    bool valid = (t != IGNORE_INDEX);
    acc += valid ? (w * nll) : 0.0f;
    cnt += valid ? 1.0f : 0.0f;
}

// min 6 blocks/SM -> reg budget ~42: enough to keep ALL six LDG.128 in flight
// (24 data regs live simultaneously), unlike the 32-reg build which serialized
// the loads into dependent batches and exposed DRAM latency.
__global__ void __launch_bounds__(TPB, 6)
ce_fused_kernel(const float* __restrict__ pred,
                const int* __restrict__ target,
                const int* __restrict__ me,
                float* __restrict__ out) {
    float acc = 0.0f, cnt = 0.0f;

    const int i = blockIdx.x * TPB + threadIdx.x;   // group index in [0, NVEC)
    const int p = i << 2;                           // first pixel of this group
    const int b = p >> 18;                          // p / HW  (HW = 2^18)
    const int hw = p & (HW - 1);
    const size_t base = (size_t)b * (NUM_CLASSES * (size_t)HW) + hw;

    // all six loads issued back-to-back (independent addresses, no consumer
    // in between) -> MLP = 6 per thread
    float4 c0 = *reinterpret_cast<const float4*>(pred + base);
    float4 c1 = *reinterpret_cast<const float4*>(pred + base + HW);
    float4 c2 = *reinterpret_cast<const float4*>(pred + base + 2 * (size_t)HW);
    float4 c3 = *reinterpret_cast<const float4*>(pred + base + 3 * (size_t)HW);
    int4 tg = *reinterpret_cast<const int4*>(target + p);
    int4 mv = *reinterpret_cast<const int4*>(me + p);

    pixel_nll(c0.x, c1.x, c2.x, c3.x, tg.x, mv.x, acc, cnt);
    pixel_nll(c0.y, c1.y, c2.y, c3.y, tg.y, mv.y, acc, cnt);
    pixel_nll(c0.z, c1.z, c2.z, c3.z, tg.z, mv.z, acc, cnt);
    pixel_nll(c0.w, c1.w, c2.w, c3.w, tg.w, mv.w, acc, cnt);

    // warp reduction
    #pragma unroll
    for (int off = 16; off > 0; off >>= 1) {
        acc += __shfl_down_sync(0xFFFFFFFFu, acc, off);
        cnt += __shfl_down_sync(0xFFFFFFFFu, cnt, off);
    }

    // block reduction across 8 warps
    __shared__ float s_acc[8];
    __shared__ float s_cnt[8];
    __shared__ bool  s_last;
    const int wid = threadIdx.x >> 5;
    const int lid = threadIdx.x & 31;
    if (lid == 0) { s_acc[wid] = acc; s_cnt[wid] = cnt; }
    __syncthreads();
    if (threadIdx.x == 0) {
        float a = 0.0f, c = 0.0f;
        #pragma unroll
        for (int w = 0; w < 8; w++) { a += s_acc[w]; c += s_cnt[w]; }
        g_partials[blockIdx.x] = make_float2(a, c);
        __threadfence();
        unsigned old = atomicInc(&g_ticket, GRID - 1);  // wraps to 0 after last block
        s_last = (old == GRID - 1);
    }
    __syncthreads();

    // last-arriving block reduces all partials and writes the scalar
    if (s_last) {
        float a = 0.0f, c = 0.0f;
        #pragma unroll
        for (int k = 0; k < GRID / TPB; k++) {          // 16 partials per thread
            float2 v = g_partials[threadIdx.x + k * TPB];
            a += v.x;
            c += v.y;
        }
        #pragma unroll
        for (int off = 16; off > 0; off >>= 1) {
            a += __shfl_down_sync(0xFFFFFFFFu, a, off);
            c += __shfl_down_sync(0xFFFFFFFFu, c, off);
        }
        if (lid == 0) { s_acc[wid] = a; s_cnt[wid] = c; }
        __syncthreads();
        if (threadIdx.x == 0) {
            float fa = 0.0f, fc = 0.0f;
            #pragma unroll
            for (int w = 0; w < 8; w++) { fa += s_acc[w]; fc += s_cnt[w]; }
            out[0] = fa / fc;
        }
    }
}

extern "C" void kernel_launch(void* const* d_in, const int* in_sizes, int n_in,
                              void* d_out, int out_size) {
    const float* pred   = (const float*)d_in[0];
    const int*   target = (const int*)d_in[1];
    const int*   me     = (const int*)d_in[2];
    float* out = (float*)d_out;

    ce_fused_kernel<<<GRID, TPB>>>(pred, target, me, out);
}

// round 5
// speedup vs baseline: 1.0559x; 1.0559x over previous
#include <cuda_runtime.h>
#include <cuda_bf16.h>

// Problem shape (fixed by the reference): pred [16,4,512,512] f32, target/ME [16,512,512] i32
#define NUM_CLASSES 4
#define IGNORE_INDEX 4
#define HW 262144              // 512*512 pixels per batch
#define NPIX (16 * HW)         // 4,194,304
#define NVEC (NPIX / 4)        // 1,048,576 float4-groups
#define GRID 1024
#define TPB 256
#define ITERS 4
#define GSTRIDE (GRID * TPB)   // 262,144 groups per sweep; GRID*TPB*ITERS == NVEC

__device__ float2   g_partials[GRID];   // written unconditionally every run -> no init needed
__device__ unsigned g_ticket = 0;       // self-resetting via atomicInc wrap

struct Group {
    float4 c0, c1, c2, c3;
    int4 tg, mv;
};

__device__ __forceinline__ Group load_group(const float* __restrict__ pred,
                                            const int* __restrict__ target,
                                            const int* __restrict__ me,
                                            int i) {
    Group g;
    int p = i << 2;
    int b = p >> 18;                 // p / HW (HW = 2^18)
    int hw = p & (HW - 1);
    size_t base = (size_t)b * (NUM_CLASSES * (size_t)HW) + hw;
    g.c0 = *reinterpret_cast<const float4*>(pred + base);
    g.c1 = *reinterpret_cast<const float4*>(pred + base + HW);
    g.c2 = *reinterpret_cast<const float4*>(pred + base + 2 * (size_t)HW);
    g.c3 = *reinterpret_cast<const float4*>(pred + base + 3 * (size_t)HW);
    g.tg = *reinterpret_cast<const int4*>(target + p);
    g.mv = *reinterpret_cast<const int4*>(me + p);
    return g;
}

__device__ __forceinline__ void pixel_nll(float v0, float v1, float v2, float v3,
                                          int t, int me,
                                          float& acc, float& cnt) {
    float m = fmaxf(fmaxf(v0, v1), fmaxf(v2, v3));
    float s = __expf(v0 - m) + __expf(v1 - m) + __expf(v2 - m) + __expf(v3 - m);
    float lse = m + __logf(s);
    int tc = min(t, NUM_CLASSES - 1);
    float vt = (tc == 0) ? v0 : (tc == 1) ? v1 : (tc == 2) ? v2 : v3;
    float nll = lse - vt;
    float w = (me == 0) ? 1.0f : 0.5f;
    bool valid = (t != IGNORE_INDEX);
    acc += valid ? (w * nll) : 0.0f;
    cnt += valid ? 1.0f : 0.0f;
}

__device__ __forceinline__ void process_group(const Group& g, float& acc, float& cnt) {
    pixel_nll(g.c0.x, g.c1.x, g.c2.x, g.c3.x, g.tg.x, g.mv.x, acc, cnt);
    pixel_nll(g.c0.y, g.c1.y, g.c2.y, g.c3.y, g.tg.y, g.mv.y, acc, cnt);
    pixel_nll(g.c0.z, g.c1.z, g.c2.z, g.c3.z, g.tg.z, g.mv.z, acc, cnt);
    pixel_nll(g.c0.w, g.c1.w, g.c2.w, g.c3.w, g.tg.w, g.mv.w, acc, cnt);
}

__global__ void __launch_bounds__(TPB)
ce_fused_kernel(const float* __restrict__ pred,
                const int* __restrict__ target,
                const int* __restrict__ me,
                float* __restrict__ out) {
    float acc = 0.0f, cnt = 0.0f;

    const int i0 = blockIdx.x * TPB + threadIdx.x;

    // Software-pipelined streaming: iteration k+1's 6 loads are issued BEFORE
    // iteration k's math, so the LSU has loads in flight continuously instead
    // of the burst-stall-compute duty cycle of the one-shot version.
    Group cur = load_group(pred, target, me, i0);
    #pragma unroll
    for (int k = 0; k < ITERS; k++) {
        Group nxt;
        if (k + 1 < ITERS)
            nxt = load_group(pred, target, me, i0 + (k + 1) * GSTRIDE);
        process_group(cur, acc, cnt);
        cur = nxt;
    }

    // warp reduction
    #pragma unroll
    for (int off = 16; off > 0; off >>= 1) {
        acc += __shfl_down_sync(0xFFFFFFFFu, acc, off);
        cnt += __shfl_down_sync(0xFFFFFFFFu, cnt, off);
    }

    // block reduction across 8 warps
    __shared__ float s_acc[8];
    __shared__ float s_cnt[8];
    __shared__ bool  s_last;
    const int wid = threadIdx.x >> 5;
    const int lid = threadIdx.x & 31;
    if (lid == 0) { s_acc[wid] = acc; s_cnt[wid] = cnt; }
    __syncthreads();
    if (threadIdx.x == 0) {
        float a = 0.0f, c = 0.0f;
        #pragma unroll
        for (int w = 0; w < 8; w++) { a += s_acc[w]; c += s_cnt[w]; }
        g_partials[blockIdx.x] = make_float2(a, c);
        __threadfence();
        unsigned old = atomicInc(&g_ticket, GRID - 1);  // wraps to 0 after last block
        s_last = (old == GRID - 1);
    }
    __syncthreads();

    // last-arriving block reduces the 1024 partials and writes the scalar
    if (s_last) {
        float a = 0.0f, c = 0.0f;
        #pragma unroll
        for (int k = 0; k < GRID / TPB; k++) {          // 4 partials per thread
            float2 v = g_partials[threadIdx.x + k * TPB];
            a += v.x;
            c += v.y;
        }
        #pragma unroll
        for (int off = 16; off > 0; off >>= 1) {
            a += __shfl_down_sync(0xFFFFFFFFu, a, off);
            c += __shfl_down_sync(0xFFFFFFFFu, c, off);
        }
        if (lid == 0) { s_acc[wid] = a; s_cnt[wid] = c; }
        __syncthreads();
        if (threadIdx.x == 0) {
            float fa = 0.0f, fc = 0.0f;
            #pragma unroll
            for (int w = 0; w < 8; w++) { fa += s_acc[w]; fc += s_cnt[w]; }
            out[0] = fa / fc;
        }
    }
}

extern "C" void kernel_launch(void* const* d_in, const int* in_sizes, int n_in,
                              void* d_out, int out_size) {
    const float* pred   = (const float*)d_in[0];
    const int*   target = (const int*)d_in[1];
    const int*   me     = (const int*)d_in[2];
    float* out = (float*)d_out;

    ce_fused_kernel<<<GRID, TPB>>>(pred, target, me, out);
}